// round 14
// baseline (speedup 1.0000x reference)
#include <cuda_runtime.h>
#include <cstdint>

#define BATCH 4
#define NT    2048
#define E     1024
#define D     64

// Projection K-split partials: [ks(2) x sel(3)] slices of 8192x64 floats.
// sel: 0=q, 1=k, 2=v. The attention kernel sums the two ks slices on load.
__device__ float g_ppart[6 * 8192 * 64];             // 12.6 MB

// Attention split-K partial scratch: per (b, qi, split) slice, up to 4 splits.
__device__ float g_oacc[BATCH * 64 * 4 * 32 * 64];   // 8 MB
__device__ float g_lacc[BATCH * 64 * 4 * 32];

#define PPART_SLICE (8192 * 64)

// ---------------------------------------------------------------------------
// helpers
// ---------------------------------------------------------------------------
__device__ __forceinline__ uint32_t f2tf32(float x) {
    uint32_t r;
    asm("cvt.rna.tf32.f32 %0, %1;" : "=r"(r) : "f"(x));
    return r;
}

// D += A * B  (m16n8k8, tf32 inputs, fp32 accumulate)
__device__ __forceinline__ void mma8(float c[4], const uint32_t a[4],
                                     const uint32_t b[2]) {
    asm volatile(
        "mma.sync.aligned.m16n8k8.row.col.f32.tf32.tf32.f32 "
        "{%0,%1,%2,%3}, {%4,%5,%6,%7}, {%8,%9}, {%0,%1,%2,%3};"
        : "+f"(c[0]), "+f"(c[1]), "+f"(c[2]), "+f"(c[3])
        : "r"(a[0]), "r"(a[1]), "r"(a[2]), "r"(a[3]), "r"(b[0]), "r"(b[1]));
}

// sum two partial float4s, convert to tf32 quad
__device__ __forceinline__ uint4 sum2_tf32(float4 a, float4 b) {
    return make_uint4(f2tf32(a.x + b.x), f2tf32(a.y + b.y),
                      f2tf32(a.z + b.z), f2tf32(a.w + b.w));
}

// ---------------------------------------------------------------------------
// Projection partial (unchanged from round 11): for K-half ks,
// acc = X[64rows x 512] . W[512 x 64]. Single-pass tf32, packed A smem.
// grid (128, 3, 2) = 768 CTAs.
// ---------------------------------------------------------------------------
#define PXP2 36    // Xp pitch in uint2 (32 + 4 pad)
#define PWP 68     // Ws pitch in u32  (64 + 4 pad)
#define P_SMEM_BYTES (64 * PXP2 * 8 + 64 * PWP * 4)   // 35840

__global__ __launch_bounds__(256) void proj_kernel(
    const float* __restrict__ Kin, const float* __restrict__ Qin,
    const float* __restrict__ Vin,
    const float* __restrict__ Wk, const float* __restrict__ Wq,
    const float* __restrict__ Wv)
{
    extern __shared__ uint32_t psm[];
    uint2*    Xp = (uint2*)psm;            // [64][PXP2]
    uint32_t* Ws = psm + 64 * PXP2 * 2;    // [64][PWP]

    const int tid = threadIdx.x;
    const int wid = tid >> 5, lane = tid & 31;
    const int g = lane >> 2, ti = lane & 3;
    const int wm = wid & 1, wn = wid >> 1;

    const int sel = blockIdx.y;
    const int ks  = blockIdx.z;
    const float* X; const float* W;
    if (sel == 0)      { X = Qin; W = Wq; }
    else if (sel == 1) { X = Kin; W = Wk; }
    else               { X = Vin; W = Wv; }
    const int row0 = blockIdx.x * 64;

    const int xrow = tid >> 3, xgrp = tid & 7;
    const int wr_ = tid >> 4, wc_ = (tid & 15) * 4;

    float acc[2][2][4];
    #pragma unroll
    for (int mi = 0; mi < 2; mi++)
        #pragma unroll
        for (int ni = 0; ni < 2; ni++)
            #pragma unroll
            for (int j = 0; j < 4; j++) acc[mi][ni][j] = 0.f;

    for (int c = 0; c < 8; c++) {
        const int k0 = ks * 512 + c * 64;
        float4 xlo[2], xhi[2], wv[4];
        #pragma unroll
        for (int p = 0; p < 2; p++) {
            const float* xb = &X[(size_t)(row0 + xrow + p * 32) * E + k0 + xgrp * 8];
            xlo[p] = *(const float4*)xb;
            xhi[p] = *(const float4*)(xb + 4);
        }
        #pragma unroll
        for (int p = 0; p < 4; p++)
            wv[p] = *(const float4*)&W[(size_t)(k0 + wr_ + p * 16) * D + wc_];
        __syncthreads();

        #pragma unroll
        for (int p = 0; p < 2; p++) {
            uint2* xd = &Xp[(xrow + p * 32) * PXP2 + xgrp * 4];
            xd[0] = make_uint2(f2tf32(xlo[p].x), f2tf32(xhi[p].x));
            xd[1] = make_uint2(f2tf32(xlo[p].y), f2tf32(xhi[p].y));
            xd[2] = make_uint2(f2tf32(xlo[p].z), f2tf32(xhi[p].z));
            xd[3] = make_uint2(f2tf32(xlo[p].w), f2tf32(xhi[p].w));
        }
        #pragma unroll
        for (int p = 0; p < 4; p++) {
            *(uint4*)&Ws[(wr_ + p * 16) * PWP + wc_] =
                make_uint4(f2tf32(wv[p].x), f2tf32(wv[p].y),
                           f2tf32(wv[p].z), f2tf32(wv[p].w));
        }
        __syncthreads();

        #pragma unroll
        for (int kk = 0; kk < 64; kk += 8) {
            const int grp = kk >> 3;
            uint32_t a[2][4], b[2][2];
            #pragma unroll
            for (int mi = 0; mi < 2; mi++) {
                int r = wm * 32 + mi * 16 + g;
                uint2 u = Xp[(r)     * PXP2 + grp * 4 + ti];
                uint2 v = Xp[(r + 8) * PXP2 + grp * 4 + ti];
                a[mi][0] = u.x; a[mi][1] = v.x;
                a[mi][2] = u.y; a[mi][3] = v.y;
            }
            #pragma unroll
            for (int ni = 0; ni < 2; ni++) {
                int d = wn * 16 + ni * 8 + g;
                b[ni][0] = Ws[(kk + ti)     * PWP + d];
                b[ni][1] = Ws[(kk + ti + 4) * PWP + d];
            }
            #pragma unroll
            for (int mi = 0; mi < 2; mi++)
                #pragma unroll
                for (int ni = 0; ni < 2; ni++)
                    mma8(acc[mi][ni], a[mi], b[ni]);
        }
    }

    float* O = g_ppart + (size_t)(ks * 3 + sel) * PPART_SLICE;
    #pragma unroll
    for (int mi = 0; mi < 2; mi++)
        #pragma unroll
        for (int ni = 0; ni < 2; ni++) {
            int r = row0 + wm * 32 + mi * 16 + g;
            int cc = wn * 16 + ni * 8 + 2 * ti;
            *(float2*)&O[(size_t)(r)     * D + cc] =
                make_float2(acc[mi][ni][0], acc[mi][ni][1]);
            *(float2*)&O[(size_t)(r + 8) * D + cc] =
                make_float2(acc[mi][ni][2], acc[mi][ni][3]);
        }
}

// ---------------------------------------------------------------------------
// Attention split-K partial kernel (round-11 geometry; loads sum the two
// proj K-split partials inline -- bit-identical to the old reduce kernel).
// q-tile of 32 rows (qi in [0,64)), k-tiles of 64 keys: ntk = qi/2 + 1.
// Key range split into chunks of 8 k-tiles: ns = qi/16 + 1 splits (1..4).
// ---------------------------------------------------------------------------
#define AP 68    // pitch (floats): 64 + 4 pad
#define A_SMEM_FLOATS (32 * AP + 64 * AP + 64 * AP + 32 * AP + 128)
#define A_SMEM_BYTES  (A_SMEM_FLOATS * 4)

__global__ __launch_bounds__(128) void attn_partial_kernel()
{
    extern __shared__ float smf[];
    uint32_t* Qb = (uint32_t*)smf;                  // [32][AP]
    uint32_t* Kb = Qb + 32 * AP;                    // [64][AP]
    uint32_t* Vb = Kb + 64 * AP;                    // [64][AP]
    uint32_t* Pb = Vb + 64 * AP;                    // [32][AP]
    float*    lw = (float*)(Pb + 32 * AP);          // [32][4]

    int G = 0;
    #pragma unroll
    for (int gg = 1; gg < 4; gg++)
        if ((int)blockIdx.x >= 8 * gg * (gg + 1)) G = gg;
    const int rem   = blockIdx.x - 8 * G * (G + 1);
    const int qi    = 16 * G + rem / (G + 1);
    const int split = rem % (G + 1);
    const int b  = blockIdx.y;
    const int q0 = qi * 32;
    const int ntk = qi / 2 + 1;
    const int t0 = split * 8;
    const int t1 = min(t0 + 8, ntk);
    const int tdiag = qi / 2;

    const int tid = threadIdx.x;
    const int wid = tid >> 5, lane = tid & 31;
    const int g = lane >> 2, ti = lane & 3;
    const int n0 = wid * 16;

    const size_t boff = (size_t)b * NT * D;
    const float* qp0 = g_ppart + 0 * PPART_SLICE + boff;
    const float* qp1 = g_ppart + 3 * PPART_SLICE + boff;
    const float* kp0 = g_ppart + 1 * PPART_SLICE + boff;
    const float* kp1 = g_ppart + 4 * PPART_SLICE + boff;
    const float* vp0 = g_ppart + 2 * PPART_SLICE + boff;
    const float* vp1 = g_ppart + 5 * PPART_SLICE + boff;

    // Load Q tile 32x64: sum both K-split partials, then tf32-round
    #pragma unroll
    for (int p = 0; p < 4; p++) {
        int i = tid + p * 128;
        int r = i >> 4, c4 = i & 15;
        size_t off = (size_t)(q0 + r) * D + c4 * 4;
        float4 a0 = *(const float4*)&qp0[off];
        float4 a1 = *(const float4*)&qp1[off];
        *(uint4*)&Qb[r * AP + c4 * 4] = sum2_tf32(a0, a1);
    }

    float accO[2][2][4];
    #pragma unroll
    for (int mi = 0; mi < 2; mi++)
        #pragma unroll
        for (int ni = 0; ni < 2; ni++)
            #pragma unroll
            for (int j = 0; j < 4; j++) accO[mi][ni][j] = 0.f;
    float rowsum[4] = {0.f, 0.f, 0.f, 0.f};

    for (int t = t0; t < t1; t++) {
        const int k0 = t * 64;
        __syncthreads();
        // Load K, V tiles 64x64: sum partials, tf32-round
        #pragma unroll
        for (int p = 0; p < 8; p++) {
            int i = tid + p * 128;
            int r = i >> 4, c4 = i & 15;
            size_t off = (size_t)(k0 + r) * D + c4 * 4;
            float4 k0v = *(const float4*)&kp0[off];
            float4 k1v = *(const float4*)&kp1[off];
            float4 v0v = *(const float4*)&vp0[off];
            float4 v1v = *(const float4*)&vp1[off];
            *(uint4*)&Kb[r * AP + c4 * 4] = sum2_tf32(k0v, k1v);
            *(uint4*)&Vb[r * AP + c4 * 4] = sum2_tf32(v0v, v1v);
        }
        __syncthreads();

        // S = Q . K^T  (32 x 64, K=64)
        float accS[2][2][4];
        #pragma unroll
        for (int mi = 0; mi < 2; mi++)
            #pragma unroll
            for (int ni = 0; ni < 2; ni++)
                #pragma unroll
                for (int j = 0; j < 4; j++) accS[mi][ni][j] = 0.f;

        #pragma unroll
        for (int kk = 0; kk < 64; kk += 8) {
            uint32_t a[2][4], bb[2][2];
            #pragma unroll
            for (int mi = 0; mi < 2; mi++) {
                int r = mi * 16 + g;
                a[mi][0] = Qb[(r)     * AP + kk + ti];
                a[mi][1] = Qb[(r + 8) * AP + kk + ti];
                a[mi][2] = Qb[(r)     * AP + kk + ti + 4];
                a[mi][3] = Qb[(r + 8) * AP + kk + ti + 4];
            }
            #pragma unroll
            for (int ni = 0; ni < 2; ni++) {
                int tok = n0 + ni * 8 + g;
                bb[ni][0] = Kb[tok * AP + kk + ti];
                bb[ni][1] = Kb[tok * AP + kk + ti + 4];
            }
            #pragma unroll
            for (int mi = 0; mi < 2; mi++)
                #pragma unroll
                for (int ni = 0; ni < 2; ni++)
                    mma8(accS[mi][ni], a[mi], bb[ni]);
        }

        // exp + (diagonal-tile-only) causal mask, stage P, accumulate l
        const bool diag = (t == tdiag);
        #pragma unroll
        for (int mi = 0; mi < 2; mi++)
            #pragma unroll
            for (int ni = 0; ni < 2; ni++)
                #pragma unroll
                for (int j = 0; j < 4; j++) {
                    int jr = j >> 1, jc = j & 1;
                    int r = mi * 16 + g + jr * 8;
                    int cc = n0 + ni * 8 + 2 * ti + jc;
                    float pex = __expf(accS[mi][ni][j] * 0.125f);
                    if (diag && (k0 + cc > q0 + r)) pex = 0.f;
                    uint32_t pt = f2tf32(pex);
                    Pb[r * AP + cc] = pt;
                    rowsum[mi * 2 + jr] += __uint_as_float(pt);
                }
        __syncthreads();

        // O += P . V  (32 x 64, K=64)
        #pragma unroll
        for (int kk = 0; kk < 64; kk += 8) {
            uint32_t a[2][4], bb[2][2];
            #pragma unroll
            for (int mi = 0; mi < 2; mi++) {
                int r = mi * 16 + g;
                a[mi][0] = Pb[(r)     * AP + kk + ti];
                a[mi][1] = Pb[(r + 8) * AP + kk + ti];
                a[mi][2] = Pb[(r)     * AP + kk + ti + 4];
                a[mi][3] = Pb[(r + 8) * AP + kk + ti + 4];
            }
            #pragma unroll
            for (int ni = 0; ni < 2; ni++) {
                int d = n0 + ni * 8 + g;
                bb[ni][0] = Vb[(kk + ti)     * AP + d];
                bb[ni][1] = Vb[(kk + ti + 4) * AP + d];
            }
            #pragma unroll
            for (int mi = 0; mi < 2; mi++)
                #pragma unroll
                for (int ni = 0; ni < 2; ni++)
                    mma8(accO[mi][ni], a[mi], bb[ni]);
        }
    }

    #pragma unroll
    for (int rp = 0; rp < 4; rp++) {
        rowsum[rp] += __shfl_xor_sync(0xffffffffu, rowsum[rp], 1);
        rowsum[rp] += __shfl_xor_sync(0xffffffffu, rowsum[rp], 2);
    }
    if (ti == 0)
        #pragma unroll
        for (int rp = 0; rp < 4; rp++) lw[(g + rp * 8) * 4 + wid] = rowsum[rp];
    __syncthreads();

    const size_t slice = ((size_t)b * 64 + qi) * 4 + split;
    if (tid < 32) {
        g_lacc[slice * 32 + tid] = lw[tid * 4 + 0] + lw[tid * 4 + 1] +
                                   lw[tid * 4 + 2] + lw[tid * 4 + 3];
    }
    float* op = g_oacc + slice * (32 * 64);
    #pragma unroll
    for (int mi = 0; mi < 2; mi++)
        #pragma unroll
        for (int ni = 0; ni < 2; ni++) {
            int r = mi * 16 + g;
            int cc = n0 + ni * 8 + 2 * ti;
            *(float2*)&op[(r)     * 64 + cc] =
                make_float2(accO[mi][ni][0], accO[mi][ni][1]);
            *(float2*)&op[(r + 8) * 64 + cc] =
                make_float2(accO[mi][ni][2], accO[mi][ni][3]);
        }
}

// ---------------------------------------------------------------------------
// Finalize: out[b, q0+row, :] = sum_s O_part / sum_s l_part
// (unchanged from round 11)
// ---------------------------------------------------------------------------
__global__ __launch_bounds__(256) void finalize_kernel(float* __restrict__ out)
{
    __shared__ float ls[32];
    const int qi = blockIdx.x, b = blockIdx.y;
    const int ns = qi / 16 + 1;
    const int tid = threadIdx.x;
    const size_t slice0 = ((size_t)b * 64 + qi) * 4;

    if (tid < 32) {
        float s = 0.f;
        for (int sp = 0; sp < ns; sp++) s += g_lacc[(slice0 + sp) * 32 + tid];
        ls[tid] = 1.f / s;
    }
    __syncthreads();

    #pragma unroll
    for (int e = 0; e < 2; e++) {
        int q4 = tid + e * 256;
        int row = q4 >> 4, c4 = q4 & 15;
        float4 s = make_float4(0.f, 0.f, 0.f, 0.f);
        for (int sp = 0; sp < ns; sp++) {
            float4 v = *(const float4*)&g_oacc[(slice0 + sp) * 2048 + row * 64 + c4 * 4];
            s.x += v.x; s.y += v.y; s.z += v.z; s.w += v.w;
        }
        float li = ls[row];
        s.x *= li; s.y *= li; s.z *= li; s.w *= li;
        *(float4*)&out[((size_t)b * NT + qi * 32 + row) * D + c4 * 4] = s;
    }
}

// ---------------------------------------------------------------------------
// Inputs (dict order): K, Q, V, Wk, Wq, Wv.  Output [B, NT, D] fp32.
// ---------------------------------------------------------------------------
extern "C" void kernel_launch(void* const* d_in, const int* in_sizes, int n_in,
                              void* d_out, int out_size)
{
    const float* Kin = (const float*)d_in[0];
    const float* Qin = (const float*)d_in[1];
    const float* Vin = (const float*)d_in[2];
    const float* Wk  = (const float*)d_in[3];
    const float* Wq  = (const float*)d_in[4];
    const float* Wv  = (const float*)d_in[5];
    float* out = (float*)d_out;
    (void)in_sizes; (void)n_in; (void)out_size;

    cudaFuncSetAttribute(proj_kernel,
                         cudaFuncAttributeMaxDynamicSharedMemorySize,
                         P_SMEM_BYTES);
    cudaFuncSetAttribute(attn_partial_kernel,
                         cudaFuncAttributeMaxDynamicSharedMemorySize,
                         A_SMEM_BYTES);

    dim3 pgrid(128, 3, 2);
    proj_kernel<<<pgrid, 256, P_SMEM_BYTES>>>(Kin, Qin, Vin, Wk, Wq, Wv);

    dim3 agrid(160, BATCH);
    attn_partial_kernel<<<agrid, 128, A_SMEM_BYTES>>>();

    dim3 fgrid(64, BATCH);
    finalize_kernel<<<fgrid, 256>>>(out);
}

// round 15
// speedup vs baseline: 1.0170x; 1.0170x over previous
#include <cuda_runtime.h>
#include <cstdint>

#define BATCH 4
#define NT    2048
#define E     1024
#define D     64

// Projected q, k, v: [B, NT, D] fp32.
__device__ float g_q[BATCH * NT * D];
__device__ float g_k[BATCH * NT * D];
__device__ float g_v[BATCH * NT * D];

// Projection K-split partials: [ks(2) x sel(3)] slices of 8192x64 floats.
__device__ float g_ppart[6 * 8192 * 64];             // 12.6 MB

// Attention split-K partial scratch: per (b, qi, split) slice, up to 4 splits.
__device__ float g_oacc[BATCH * 64 * 4 * 32 * 64];   // 8 MB
__device__ float g_lacc[BATCH * 64 * 4 * 32];

#define PPART_SLICE (8192 * 64)

// ---------------------------------------------------------------------------
// helpers
// ---------------------------------------------------------------------------
__device__ __forceinline__ uint32_t f2tf32(float x) {
    uint32_t r;
    asm("cvt.rna.tf32.f32 %0, %1;" : "=r"(r) : "f"(x));
    return r;
}

// D += A * B  (m16n8k8, tf32 inputs, fp32 accumulate)
__device__ __forceinline__ void mma8(float c[4], const uint32_t a[4],
                                     const uint32_t b[2]) {
    asm volatile(
        "mma.sync.aligned.m16n8k8.row.col.f32.tf32.tf32.f32 "
        "{%0,%1,%2,%3}, {%4,%5,%6,%7}, {%8,%9}, {%0,%1,%2,%3};"
        : "+f"(c[0]), "+f"(c[1]), "+f"(c[2]), "+f"(c[3])
        : "r"(a[0]), "r"(a[1]), "r"(a[2]), "r"(a[3]), "r"(b[0]), "r"(b[1]));
}

// ---------------------------------------------------------------------------
// Projection partial (round-11, unchanged): for K-half ks,
// acc = X[64rows x 512] . W[512 x 64]. Single-pass tf32, packed A smem.
// grid (128, 3, 2) = 768 CTAs.
// ---------------------------------------------------------------------------
#define PXP2 36    // Xp pitch in uint2 (32 + 4 pad)
#define PWP 68     // Ws pitch in u32  (64 + 4 pad)
#define P_SMEM_BYTES (64 * PXP2 * 8 + 64 * PWP * 4)   // 35840

__global__ __launch_bounds__(256) void proj_kernel(
    const float* __restrict__ Kin, const float* __restrict__ Qin,
    const float* __restrict__ Vin,
    const float* __restrict__ Wk, const float* __restrict__ Wq,
    const float* __restrict__ Wv)
{
    extern __shared__ uint32_t psm[];
    uint2*    Xp = (uint2*)psm;            // [64][PXP2]
    uint32_t* Ws = psm + 64 * PXP2 * 2;    // [64][PWP]

    const int tid = threadIdx.x;
    const int wid = tid >> 5, lane = tid & 31;
    const int g = lane >> 2, ti = lane & 3;
    const int wm = wid & 1, wn = wid >> 1;

    const int sel = blockIdx.y;
    const int ks  = blockIdx.z;
    const float* X; const float* W;
    if (sel == 0)      { X = Qin; W = Wq; }
    else if (sel == 1) { X = Kin; W = Wk; }
    else               { X = Vin; W = Wv; }
    const int row0 = blockIdx.x * 64;

    const int xrow = tid >> 3, xgrp = tid & 7;
    const int wr_ = tid >> 4, wc_ = (tid & 15) * 4;

    float acc[2][2][4];
    #pragma unroll
    for (int mi = 0; mi < 2; mi++)
        #pragma unroll
        for (int ni = 0; ni < 2; ni++)
            #pragma unroll
            for (int j = 0; j < 4; j++) acc[mi][ni][j] = 0.f;

    for (int c = 0; c < 8; c++) {
        const int k0 = ks * 512 + c * 64;
        float4 xlo[2], xhi[2], wv[4];
        #pragma unroll
        for (int p = 0; p < 2; p++) {
            const float* xb = &X[(size_t)(row0 + xrow + p * 32) * E + k0 + xgrp * 8];
            xlo[p] = *(const float4*)xb;
            xhi[p] = *(const float4*)(xb + 4);
        }
        #pragma unroll
        for (int p = 0; p < 4; p++)
            wv[p] = *(const float4*)&W[(size_t)(k0 + wr_ + p * 16) * D + wc_];
        __syncthreads();

        #pragma unroll
        for (int p = 0; p < 2; p++) {
            uint2* xd = &Xp[(xrow + p * 32) * PXP2 + xgrp * 4];
            xd[0] = make_uint2(f2tf32(xlo[p].x), f2tf32(xhi[p].x));
            xd[1] = make_uint2(f2tf32(xlo[p].y), f2tf32(xhi[p].y));
            xd[2] = make_uint2(f2tf32(xlo[p].z), f2tf32(xhi[p].z));
            xd[3] = make_uint2(f2tf32(xlo[p].w), f2tf32(xhi[p].w));
        }
        #pragma unroll
        for (int p = 0; p < 4; p++) {
            *(uint4*)&Ws[(wr_ + p * 16) * PWP + wc_] =
                make_uint4(f2tf32(wv[p].x), f2tf32(wv[p].y),
                           f2tf32(wv[p].z), f2tf32(wv[p].w));
        }
        __syncthreads();

        #pragma unroll
        for (int kk = 0; kk < 64; kk += 8) {
            const int grp = kk >> 3;
            uint32_t a[2][4], b[2][2];
            #pragma unroll
            for (int mi = 0; mi < 2; mi++) {
                int r = wm * 32 + mi * 16 + g;
                uint2 u = Xp[(r)     * PXP2 + grp * 4 + ti];
                uint2 v = Xp[(r + 8) * PXP2 + grp * 4 + ti];
                a[mi][0] = u.x; a[mi][1] = v.x;
                a[mi][2] = u.y; a[mi][3] = v.y;
            }
            #pragma unroll
            for (int ni = 0; ni < 2; ni++) {
                int d = wn * 16 + ni * 8 + g;
                b[ni][0] = Ws[(kk + ti)     * PWP + d];
                b[ni][1] = Ws[(kk + ti + 4) * PWP + d];
            }
            #pragma unroll
            for (int mi = 0; mi < 2; mi++)
                #pragma unroll
                for (int ni = 0; ni < 2; ni++)
                    mma8(acc[mi][ni], a[mi], b[ni]);
        }
    }

    float* O = g_ppart + (size_t)(ks * 3 + sel) * PPART_SLICE;
    #pragma unroll
    for (int mi = 0; mi < 2; mi++)
        #pragma unroll
        for (int ni = 0; ni < 2; ni++) {
            int r = row0 + wm * 32 + mi * 16 + g;
            int cc = wn * 16 + ni * 8 + 2 * ti;
            *(float2*)&O[(size_t)(r)     * D + cc] =
                make_float2(acc[mi][ni][0], acc[mi][ni][1]);
            *(float2*)&O[(size_t)(r + 8) * D + cc] =
                make_float2(acc[mi][ni][2], acc[mi][ni][3]);
        }
}

// ---------------------------------------------------------------------------
// Reduce the two K-split proj partials into g_q / g_k / g_v (round-11).
// ---------------------------------------------------------------------------
__global__ __launch_bounds__(256) void proj_reduce_kernel()
{
    const int sel = blockIdx.y;
    const size_t idx4 = (size_t)blockIdx.x * 256 + threadIdx.x;  // < 131072
    const float4* p0 = (const float4*)(g_ppart + (size_t)sel * PPART_SLICE);
    const float4* p1 = (const float4*)(g_ppart + (size_t)(3 + sel) * PPART_SLICE);
    float4 a = p0[idx4], b = p1[idx4];
    float4 s = make_float4(a.x + b.x, a.y + b.y, a.z + b.z, a.w + b.w);
    float* dst = (sel == 0) ? g_q : (sel == 1) ? g_k : g_v;
    ((float4*)dst)[idx4] = s;
}

// ---------------------------------------------------------------------------
// Attention split-K partial kernel (round-11 geometry, BALANCED splits).
// q-tile of 32 rows (qi in [0,64)), k-tiles of 64 keys: ntk = qi/2 + 1.
// ns = qi/16 + 1 splits; split s covers base+(s<rem) tiles (balanced),
// e.g. ntk=17 -> 6,6,5 instead of 8,8,1: flatter CTA durations.
// ---------------------------------------------------------------------------
#define AP 68    // pitch (floats): 64 + 4 pad
#define A_SMEM_FLOATS (32 * AP + 64 * AP + 64 * AP + 32 * AP + 128)
#define A_SMEM_BYTES  (A_SMEM_FLOATS * 4)

__global__ __launch_bounds__(128) void attn_partial_kernel()
{
    extern __shared__ float smf[];
    uint32_t* Qb = (uint32_t*)smf;                  // [32][AP]
    uint32_t* Kb = Qb + 32 * AP;                    // [64][AP]
    uint32_t* Vb = Kb + 64 * AP;                    // [64][AP]
    uint32_t* Pb = Vb + 64 * AP;                    // [32][AP]
    float*    lw = (float*)(Pb + 32 * AP);          // [32][4]

    int G = 0;
    #pragma unroll
    for (int gg = 1; gg < 4; gg++)
        if ((int)blockIdx.x >= 8 * gg * (gg + 1)) G = gg;
    const int rem_  = blockIdx.x - 8 * G * (G + 1);
    const int qi    = 16 * G + rem_ / (G + 1);
    const int split = rem_ % (G + 1);
    const int b  = blockIdx.y;
    const int q0 = qi * 32;
    const int ntk = qi / 2 + 1;
    const int ns  = G + 1;
    const int base = ntk / ns, rm = ntk % ns;
    const int t0 = split * base + min(split, rm);
    const int t1 = t0 + base + (split < rm ? 1 : 0);
    const int tdiag = qi / 2;

    const int tid = threadIdx.x;
    const int wid = tid >> 5, lane = tid & 31;
    const int g = lane >> 2, ti = lane & 3;
    const int n0 = wid * 16;

    const float* qp = g_q + (size_t)b * NT * D;
    const float* kp = g_k + (size_t)b * NT * D;
    const float* vp = g_v + (size_t)b * NT * D;

    // Load Q tile 32x64 (tf32-rounded)
    #pragma unroll
    for (int p = 0; p < 4; p++) {
        int i = tid + p * 128;
        int r = i >> 4, c4 = i & 15;
        float4 v = *(const float4*)&qp[(size_t)(q0 + r) * D + c4 * 4];
        *(uint4*)&Qb[r * AP + c4 * 4] =
            make_uint4(f2tf32(v.x), f2tf32(v.y), f2tf32(v.z), f2tf32(v.w));
    }

    float accO[2][2][4];
    #pragma unroll
    for (int mi = 0; mi < 2; mi++)
        #pragma unroll
        for (int ni = 0; ni < 2; ni++)
            #pragma unroll
            for (int j = 0; j < 4; j++) accO[mi][ni][j] = 0.f;
    float rowsum[4] = {0.f, 0.f, 0.f, 0.f};

    for (int t = t0; t < t1; t++) {
        const int k0 = t * 64;
        __syncthreads();
        #pragma unroll
        for (int p = 0; p < 8; p++) {
            int i = tid + p * 128;
            int r = i >> 4, c4 = i & 15;
            float4 kv = *(const float4*)&kp[(size_t)(k0 + r) * D + c4 * 4];
            float4 vv = *(const float4*)&vp[(size_t)(k0 + r) * D + c4 * 4];
            *(uint4*)&Kb[r * AP + c4 * 4] =
                make_uint4(f2tf32(kv.x), f2tf32(kv.y), f2tf32(kv.z), f2tf32(kv.w));
            *(uint4*)&Vb[r * AP + c4 * 4] =
                make_uint4(f2tf32(vv.x), f2tf32(vv.y), f2tf32(vv.z), f2tf32(vv.w));
        }
        __syncthreads();

        // S = Q . K^T  (32 x 64, K=64)
        float accS[2][2][4];
        #pragma unroll
        for (int mi = 0; mi < 2; mi++)
            #pragma unroll
            for (int ni = 0; ni < 2; ni++)
                #pragma unroll
                for (int j = 0; j < 4; j++) accS[mi][ni][j] = 0.f;

        #pragma unroll
        for (int kk = 0; kk < 64; kk += 8) {
            uint32_t a[2][4], bb[2][2];
            #pragma unroll
            for (int mi = 0; mi < 2; mi++) {
                int r = mi * 16 + g;
                a[mi][0] = Qb[(r)     * AP + kk + ti];
                a[mi][1] = Qb[(r + 8) * AP + kk + ti];
                a[mi][2] = Qb[(r)     * AP + kk + ti + 4];
                a[mi][3] = Qb[(r + 8) * AP + kk + ti + 4];
            }
            #pragma unroll
            for (int ni = 0; ni < 2; ni++) {
                int tok = n0 + ni * 8 + g;
                bb[ni][0] = Kb[tok * AP + kk + ti];
                bb[ni][1] = Kb[tok * AP + kk + ti + 4];
            }
            #pragma unroll
            for (int mi = 0; mi < 2; mi++)
                #pragma unroll
                for (int ni = 0; ni < 2; ni++)
                    mma8(accS[mi][ni], a[mi], bb[ni]);
        }

        // exp + (diagonal-tile-only) causal mask, stage P, accumulate l
        const bool diag = (t == tdiag);
        #pragma unroll
        for (int mi = 0; mi < 2; mi++)
            #pragma unroll
            for (int ni = 0; ni < 2; ni++)
                #pragma unroll
                for (int j = 0; j < 4; j++) {
                    int jr = j >> 1, jc = j & 1;
                    int r = mi * 16 + g + jr * 8;
                    int cc = n0 + ni * 8 + 2 * ti + jc;
                    float pex = __expf(accS[mi][ni][j] * 0.125f);
                    if (diag && (k0 + cc > q0 + r)) pex = 0.f;
                    uint32_t pt = f2tf32(pex);
                    Pb[r * AP + cc] = pt;
                    rowsum[mi * 2 + jr] += __uint_as_float(pt);
                }
        __syncthreads();

        // O += P . V  (32 x 64, K=64)
        #pragma unroll
        for (int kk = 0; kk < 64; kk += 8) {
            uint32_t a[2][4], bb[2][2];
            #pragma unroll
            for (int mi = 0; mi < 2; mi++) {
                int r = mi * 16 + g;
                a[mi][0] = Pb[(r)     * AP + kk + ti];
                a[mi][1] = Pb[(r + 8) * AP + kk + ti];
                a[mi][2] = Pb[(r)     * AP + kk + ti + 4];
                a[mi][3] = Pb[(r + 8) * AP + kk + ti + 4];
            }
            #pragma unroll
            for (int ni = 0; ni < 2; ni++) {
                int d = n0 + ni * 8 + g;
                bb[ni][0] = Vb[(kk + ti)     * AP + d];
                bb[ni][1] = Vb[(kk + ti + 4) * AP + d];
            }
            #pragma unroll
            for (int mi = 0; mi < 2; mi++)
                #pragma unroll
                for (int ni = 0; ni < 2; ni++)
                    mma8(accO[mi][ni], a[mi], bb[ni]);
        }
    }

    #pragma unroll
    for (int rp = 0; rp < 4; rp++) {
        rowsum[rp] += __shfl_xor_sync(0xffffffffu, rowsum[rp], 1);
        rowsum[rp] += __shfl_xor_sync(0xffffffffu, rowsum[rp], 2);
    }
    if (ti == 0)
        #pragma unroll
        for (int rp = 0; rp < 4; rp++) lw[(g + rp * 8) * 4 + wid] = rowsum[rp];
    __syncthreads();

    const size_t slice = ((size_t)b * 64 + qi) * 4 + split;
    if (tid < 32) {
        g_lacc[slice * 32 + tid] = lw[tid * 4 + 0] + lw[tid * 4 + 1] +
                                   lw[tid * 4 + 2] + lw[tid * 4 + 3];
    }
    float* op = g_oacc + slice * (32 * 64);
    #pragma unroll
    for (int mi = 0; mi < 2; mi++)
        #pragma unroll
        for (int ni = 0; ni < 2; ni++) {
            int r = mi * 16 + g;
            int cc = n0 + ni * 8 + 2 * ti;
            *(float2*)&op[(r)     * 64 + cc] =
                make_float2(accO[mi][ni][0], accO[mi][ni][1]);
            *(float2*)&op[(r + 8) * 64 + cc] =
                make_float2(accO[mi][ni][2], accO[mi][ni][3]);
        }
}

// ---------------------------------------------------------------------------
// Finalize: out[b, q0+row, :] = sum_s O_part / sum_s l_part
// grid (128, 4): blockIdx.x = qi*2 + half. 256 threads, 1 float4 each
// (16 rows x 16 float4 per CTA) -> 512 CTAs, better latency hiding.
// ---------------------------------------------------------------------------
__global__ __launch_bounds__(256) void finalize_kernel(float* __restrict__ out)
{
    __shared__ float ls[16];
    const int qi = blockIdx.x >> 1, half = blockIdx.x & 1;
    const int b = blockIdx.y;
    const int ns = qi / 16 + 1;
    const int tid = threadIdx.x;
    const size_t slice0 = ((size_t)b * 64 + qi) * 4;
    const int r0 = half * 16;

    if (tid < 16) {
        float s = 0.f;
        for (int sp = 0; sp < ns; sp++)
            s += g_lacc[(slice0 + sp) * 32 + r0 + tid];
        ls[tid] = 1.f / s;
    }
    __syncthreads();

    {
        int row = tid >> 4, c4 = tid & 15;      // row 0..15, c4 0..15
        float4 s = make_float4(0.f, 0.f, 0.f, 0.f);
        for (int sp = 0; sp < ns; sp++) {
            float4 v = *(const float4*)&g_oacc[(slice0 + sp) * 2048 +
                                               (r0 + row) * 64 + c4 * 4];
            s.x += v.x; s.y += v.y; s.z += v.z; s.w += v.w;
        }
        float li = ls[row];
        s.x *= li; s.y *= li; s.z *= li; s.w *= li;
        *(float4*)&out[((size_t)b * NT + qi * 32 + r0 + row) * D + c4 * 4] = s;
    }
}

// ---------------------------------------------------------------------------
// Inputs (dict order): K, Q, V, Wk, Wq, Wv.  Output [B, NT, D] fp32.
// ---------------------------------------------------------------------------
extern "C" void kernel_launch(void* const* d_in, const int* in_sizes, int n_in,
                              void* d_out, int out_size)
{
    const float* Kin = (const float*)d_in[0];
    const float* Qin = (const float*)d_in[1];
    const float* Vin = (const float*)d_in[2];
    const float* Wk  = (const float*)d_in[3];
    const float* Wq  = (const float*)d_in[4];
    const float* Wv  = (const float*)d_in[5];
    float* out = (float*)d_out;
    (void)in_sizes; (void)n_in; (void)out_size;

    cudaFuncSetAttribute(proj_kernel,
                         cudaFuncAttributeMaxDynamicSharedMemorySize,
                         P_SMEM_BYTES);
    cudaFuncSetAttribute(attn_partial_kernel,
                         cudaFuncAttributeMaxDynamicSharedMemorySize,
                         A_SMEM_BYTES);

    dim3 pgrid(128, 3, 2);
    proj_kernel<<<pgrid, 256, P_SMEM_BYTES>>>(Kin, Qin, Vin, Wk, Wq, Wv);

    dim3 rgrid(512, 3);
    proj_reduce_kernel<<<rgrid, 256>>>();

    dim3 agrid(160, BATCH);
    attn_partial_kernel<<<agrid, 128, A_SMEM_BYTES>>>();

    dim3 fgrid(128, BATCH);
    finalize_kernel<<<fgrid, 256>>>(out);
}

// round 16
// speedup vs baseline: 1.0569x; 1.0392x over previous
#include <cuda_runtime.h>
#include <cstdint>

#define BATCH 4
#define NT    2048
#define E     1024
#define D     64

// Projected q, k, v: [B, NT, D] fp32.
__device__ float g_q[BATCH * NT * D];
__device__ float g_k[BATCH * NT * D];
__device__ float g_v[BATCH * NT * D];

// Projection K-split partials: [ks(2) x sel(3)] slices of 8192x64 floats.
__device__ float g_ppart[6 * 8192 * 64];             // 12.6 MB

// Attention split-K partial scratch: per (b, qi, split) slice, up to 4 splits.
__device__ float g_oacc[BATCH * 64 * 4 * 32 * 64];   // 8 MB
__device__ float g_lacc[BATCH * 64 * 4 * 32];

#define PPART_SLICE (8192 * 64)

// ---------------------------------------------------------------------------
// helpers
// ---------------------------------------------------------------------------
__device__ __forceinline__ uint32_t f2tf32(float x) {
    uint32_t r;
    asm("cvt.rna.tf32.f32 %0, %1;" : "=r"(r) : "f"(x));
    return r;
}

// D += A * B  (m16n8k8, tf32 inputs, fp32 accumulate)
__device__ __forceinline__ void mma8(float c[4], const uint32_t a[4],
                                     const uint32_t b[2]) {
    asm volatile(
        "mma.sync.aligned.m16n8k8.row.col.f32.tf32.tf32.f32 "
        "{%0,%1,%2,%3}, {%4,%5,%6,%7}, {%8,%9}, {%0,%1,%2,%3};"
        : "+f"(c[0]), "+f"(c[1]), "+f"(c[2]), "+f"(c[3])
        : "r"(a[0]), "r"(a[1]), "r"(a[2]), "r"(a[3]), "r"(b[0]), "r"(b[1]));
}

// ---------------------------------------------------------------------------
// Projection partial (round-11, unchanged): for K-half ks,
// acc = X[64rows x 512] . W[512 x 64]. Single-pass tf32, packed A smem.
// grid (128, 3, 2) = 768 CTAs.
// ---------------------------------------------------------------------------
#define PXP2 36    // Xp pitch in uint2 (32 + 4 pad)
#define PWP 68     // Ws pitch in u32  (64 + 4 pad)
#define P_SMEM_BYTES (64 * PXP2 * 8 + 64 * PWP * 4)   // 35840

__global__ __launch_bounds__(256) void proj_kernel(
    const float* __restrict__ Kin, const float* __restrict__ Qin,
    const float* __restrict__ Vin,
    const float* __restrict__ Wk, const float* __restrict__ Wq,
    const float* __restrict__ Wv)
{
    extern __shared__ uint32_t psm[];
    uint2*    Xp = (uint2*)psm;            // [64][PXP2]
    uint32_t* Ws = psm + 64 * PXP2 * 2;    // [64][PWP]

    const int tid = threadIdx.x;
    const int wid = tid >> 5, lane = tid & 31;
    const int g = lane >> 2, ti = lane & 3;
    const int wm = wid & 1, wn = wid >> 1;

    const int sel = blockIdx.y;
    const int ks  = blockIdx.z;
    const float* X; const float* W;
    if (sel == 0)      { X = Qin; W = Wq; }
    else if (sel == 1) { X = Kin; W = Wk; }
    else               { X = Vin; W = Wv; }
    const int row0 = blockIdx.x * 64;

    const int xrow = tid >> 3, xgrp = tid & 7;
    const int wr_ = tid >> 4, wc_ = (tid & 15) * 4;

    float acc[2][2][4];
    #pragma unroll
    for (int mi = 0; mi < 2; mi++)
        #pragma unroll
        for (int ni = 0; ni < 2; ni++)
            #pragma unroll
            for (int j = 0; j < 4; j++) acc[mi][ni][j] = 0.f;

    for (int c = 0; c < 8; c++) {
        const int k0 = ks * 512 + c * 64;
        float4 xlo[2], xhi[2], wv[4];
        #pragma unroll
        for (int p = 0; p < 2; p++) {
            const float* xb = &X[(size_t)(row0 + xrow + p * 32) * E + k0 + xgrp * 8];
            xlo[p] = *(const float4*)xb;
            xhi[p] = *(const float4*)(xb + 4);
        }
        #pragma unroll
        for (int p = 0; p < 4; p++)
            wv[p] = *(const float4*)&W[(size_t)(k0 + wr_ + p * 16) * D + wc_];
        __syncthreads();

        #pragma unroll
        for (int p = 0; p < 2; p++) {
            uint2* xd = &Xp[(xrow + p * 32) * PXP2 + xgrp * 4];
            xd[0] = make_uint2(f2tf32(xlo[p].x), f2tf32(xhi[p].x));
            xd[1] = make_uint2(f2tf32(xlo[p].y), f2tf32(xhi[p].y));
            xd[2] = make_uint2(f2tf32(xlo[p].z), f2tf32(xhi[p].z));
            xd[3] = make_uint2(f2tf32(xlo[p].w), f2tf32(xhi[p].w));
        }
        #pragma unroll
        for (int p = 0; p < 4; p++) {
            *(uint4*)&Ws[(wr_ + p * 16) * PWP + wc_] =
                make_uint4(f2tf32(wv[p].x), f2tf32(wv[p].y),
                           f2tf32(wv[p].z), f2tf32(wv[p].w));
        }
        __syncthreads();

        #pragma unroll
        for (int kk = 0; kk < 64; kk += 8) {
            const int grp = kk >> 3;
            uint32_t a[2][4], b[2][2];
            #pragma unroll
            for (int mi = 0; mi < 2; mi++) {
                int r = wm * 32 + mi * 16 + g;
                uint2 u = Xp[(r)     * PXP2 + grp * 4 + ti];
                uint2 v = Xp[(r + 8) * PXP2 + grp * 4 + ti];
                a[mi][0] = u.x; a[mi][1] = v.x;
                a[mi][2] = u.y; a[mi][3] = v.y;
            }
            #pragma unroll
            for (int ni = 0; ni < 2; ni++) {
                int d = wn * 16 + ni * 8 + g;
                b[ni][0] = Ws[(kk + ti)     * PWP + d];
                b[ni][1] = Ws[(kk + ti + 4) * PWP + d];
            }
            #pragma unroll
            for (int mi = 0; mi < 2; mi++)
                #pragma unroll
                for (int ni = 0; ni < 2; ni++)
                    mma8(acc[mi][ni], a[mi], b[ni]);
        }
    }

    float* O = g_ppart + (size_t)(ks * 3 + sel) * PPART_SLICE;
    #pragma unroll
    for (int mi = 0; mi < 2; mi++)
        #pragma unroll
        for (int ni = 0; ni < 2; ni++) {
            int r = row0 + wm * 32 + mi * 16 + g;
            int cc = wn * 16 + ni * 8 + 2 * ti;
            *(float2*)&O[(size_t)(r)     * D + cc] =
                make_float2(acc[mi][ni][0], acc[mi][ni][1]);
            *(float2*)&O[(size_t)(r + 8) * D + cc] =
                make_float2(acc[mi][ni][2], acc[mi][ni][3]);
        }
}

// ---------------------------------------------------------------------------
// Reduce the two K-split proj partials into g_q / g_k / g_v (round-11).
// ---------------------------------------------------------------------------
__global__ __launch_bounds__(256) void proj_reduce_kernel()
{
    const int sel = blockIdx.y;
    const size_t idx4 = (size_t)blockIdx.x * 256 + threadIdx.x;  // < 131072
    const float4* p0 = (const float4*)(g_ppart + (size_t)sel * PPART_SLICE);
    const float4* p1 = (const float4*)(g_ppart + (size_t)(3 + sel) * PPART_SLICE);
    float4 a = p0[idx4], b = p1[idx4];
    float4 s = make_float4(a.x + b.x, a.y + b.y, a.z + b.z, a.w + b.w);
    float* dst = (sel == 0) ? g_q : (sel == 1) ? g_k : g_v;
    ((float4*)dst)[idx4] = s;
}

// ---------------------------------------------------------------------------
// Attention split-K partial kernel (byte-identical to round-11 PASS).
// q-tile of 32 rows (qi in [0,64)), k-tiles of 64 keys: ntk = qi/2 + 1.
// Key range split into chunks of 8 k-tiles: ns = qi/16 + 1 splits (1..4).
// ---------------------------------------------------------------------------
#define AP 68    // pitch (floats): 64 + 4 pad
#define A_SMEM_FLOATS (32 * AP + 64 * AP + 64 * AP + 32 * AP + 128)
#define A_SMEM_BYTES  (A_SMEM_FLOATS * 4)

__global__ __launch_bounds__(128) void attn_partial_kernel()
{
    extern __shared__ float smf[];
    uint32_t* Qb = (uint32_t*)smf;                  // [32][AP]
    uint32_t* Kb = Qb + 32 * AP;                    // [64][AP]
    uint32_t* Vb = Kb + 64 * AP;                    // [64][AP]
    uint32_t* Pb = Vb + 64 * AP;                    // [32][AP]
    float*    lw = (float*)(Pb + 32 * AP);          // [32][4]

    int G = 0;
    #pragma unroll
    for (int gg = 1; gg < 4; gg++)
        if ((int)blockIdx.x >= 8 * gg * (gg + 1)) G = gg;
    const int rem   = blockIdx.x - 8 * G * (G + 1);
    const int qi    = 16 * G + rem / (G + 1);
    const int split = rem % (G + 1);
    const int b  = blockIdx.y;
    const int q0 = qi * 32;
    const int ntk = qi / 2 + 1;
    const int t0 = split * 8;
    const int t1 = min(t0 + 8, ntk);
    const int tdiag = qi / 2;

    const int tid = threadIdx.x;
    const int wid = tid >> 5, lane = tid & 31;
    const int g = lane >> 2, ti = lane & 3;
    const int n0 = wid * 16;

    const float* qp = g_q + (size_t)b * NT * D;
    const float* kp = g_k + (size_t)b * NT * D;
    const float* vp = g_v + (size_t)b * NT * D;

    #pragma unroll
    for (int p = 0; p < 4; p++) {
        int i = tid + p * 128;
        int r = i >> 4, c4 = i & 15;
        float4 v = *(const float4*)&qp[(size_t)(q0 + r) * D + c4 * 4];
        *(uint4*)&Qb[r * AP + c4 * 4] =
            make_uint4(f2tf32(v.x), f2tf32(v.y), f2tf32(v.z), f2tf32(v.w));
    }

    float accO[2][2][4];
    #pragma unroll
    for (int mi = 0; mi < 2; mi++)
        #pragma unroll
        for (int ni = 0; ni < 2; ni++)
            #pragma unroll
            for (int j = 0; j < 4; j++) accO[mi][ni][j] = 0.f;
    float rowsum[4] = {0.f, 0.f, 0.f, 0.f};

    for (int t = t0; t < t1; t++) {
        const int k0 = t * 64;
        __syncthreads();
        #pragma unroll
        for (int p = 0; p < 8; p++) {
            int i = tid + p * 128;
            int r = i >> 4, c4 = i & 15;
            float4 kv = *(const float4*)&kp[(size_t)(k0 + r) * D + c4 * 4];
            float4 vv = *(const float4*)&vp[(size_t)(k0 + r) * D + c4 * 4];
            *(uint4*)&Kb[r * AP + c4 * 4] =
                make_uint4(f2tf32(kv.x), f2tf32(kv.y), f2tf32(kv.z), f2tf32(kv.w));
            *(uint4*)&Vb[r * AP + c4 * 4] =
                make_uint4(f2tf32(vv.x), f2tf32(vv.y), f2tf32(vv.z), f2tf32(vv.w));
        }
        __syncthreads();

        float accS[2][2][4];
        #pragma unroll
        for (int mi = 0; mi < 2; mi++)
            #pragma unroll
            for (int ni = 0; ni < 2; ni++)
                #pragma unroll
                for (int j = 0; j < 4; j++) accS[mi][ni][j] = 0.f;

        #pragma unroll
        for (int kk = 0; kk < 64; kk += 8) {
            uint32_t a[2][4], bb[2][2];
            #pragma unroll
            for (int mi = 0; mi < 2; mi++) {
                int r = mi * 16 + g;
                a[mi][0] = Qb[(r)     * AP + kk + ti];
                a[mi][1] = Qb[(r + 8) * AP + kk + ti];
                a[mi][2] = Qb[(r)     * AP + kk + ti + 4];
                a[mi][3] = Qb[(r + 8) * AP + kk + ti + 4];
            }
            #pragma unroll
            for (int ni = 0; ni < 2; ni++) {
                int tok = n0 + ni * 8 + g;
                bb[ni][0] = Kb[tok * AP + kk + ti];
                bb[ni][1] = Kb[tok * AP + kk + ti + 4];
            }
            #pragma unroll
            for (int mi = 0; mi < 2; mi++)
                #pragma unroll
                for (int ni = 0; ni < 2; ni++)
                    mma8(accS[mi][ni], a[mi], bb[ni]);
        }

        const bool diag = (t == tdiag);
        #pragma unroll
        for (int mi = 0; mi < 2; mi++)
            #pragma unroll
            for (int ni = 0; ni < 2; ni++)
                #pragma unroll
                for (int j = 0; j < 4; j++) {
                    int jr = j >> 1, jc = j & 1;
                    int r = mi * 16 + g + jr * 8;
                    int cc = n0 + ni * 8 + 2 * ti + jc;
                    float pex = __expf(accS[mi][ni][j] * 0.125f);
                    if (diag && (k0 + cc > q0 + r)) pex = 0.f;
                    uint32_t pt = f2tf32(pex);
                    Pb[r * AP + cc] = pt;
                    rowsum[mi * 2 + jr] += __uint_as_float(pt);
                }
        __syncthreads();

        #pragma unroll
        for (int kk = 0; kk < 64; kk += 8) {
            uint32_t a[2][4], bb[2][2];
            #pragma unroll
            for (int mi = 0; mi < 2; mi++) {
                int r = mi * 16 + g;
                a[mi][0] = Pb[(r)     * AP + kk + ti];
                a[mi][1] = Pb[(r + 8) * AP + kk + ti];
                a[mi][2] = Pb[(r)     * AP + kk + ti + 4];
                a[mi][3] = Pb[(r + 8) * AP + kk + ti + 4];
            }
            #pragma unroll
            for (int ni = 0; ni < 2; ni++) {
                int d = n0 + ni * 8 + g;
                bb[ni][0] = Vb[(kk + ti)     * AP + d];
                bb[ni][1] = Vb[(kk + ti + 4) * AP + d];
            }
            #pragma unroll
            for (int mi = 0; mi < 2; mi++)
                #pragma unroll
                for (int ni = 0; ni < 2; ni++)
                    mma8(accO[mi][ni], a[mi], bb[ni]);
        }
    }

    #pragma unroll
    for (int rp = 0; rp < 4; rp++) {
        rowsum[rp] += __shfl_xor_sync(0xffffffffu, rowsum[rp], 1);
        rowsum[rp] += __shfl_xor_sync(0xffffffffu, rowsum[rp], 2);
    }
    if (ti == 0)
        #pragma unroll
        for (int rp = 0; rp < 4; rp++) lw[(g + rp * 8) * 4 + wid] = rowsum[rp];
    __syncthreads();

    const size_t slice = ((size_t)b * 64 + qi) * 4 + split;
    if (tid < 32) {
        g_lacc[slice * 32 + tid] = lw[tid * 4 + 0] + lw[tid * 4 + 1] +
                                   lw[tid * 4 + 2] + lw[tid * 4 + 3];
    }
    float* op = g_oacc + slice * (32 * 64);
    #pragma unroll
    for (int mi = 0; mi < 2; mi++)
        #pragma unroll
        for (int ni = 0; ni < 2; ni++) {
            int r = mi * 16 + g;
            int cc = n0 + ni * 8 + 2 * ti;
            *(float2*)&op[(r)     * 64 + cc] =
                make_float2(accO[mi][ni][0], accO[mi][ni][1]);
            *(float2*)&op[(r + 8) * 64 + cc] =
                make_float2(accO[mi][ni][2], accO[mi][ni][3]);
        }
}

// ---------------------------------------------------------------------------
// Finalize: out[b, q0+row, :] = sum_s O_part / sum_s l_part
// grid (128, 4): blockIdx.x = qi*2 + half. 256 threads, 1 float4 each
// (16 rows x 16 float4 per CTA) -> 512 CTAs (measured: 8.4 -> 6.8 us).
// ---------------------------------------------------------------------------
__global__ __launch_bounds__(256) void finalize_kernel(float* __restrict__ out)
{
    __shared__ float ls[16];
    const int qi = blockIdx.x >> 1, half = blockIdx.x & 1;
    const int b = blockIdx.y;
    const int ns = qi / 16 + 1;
    const int tid = threadIdx.x;
    const size_t slice0 = ((size_t)b * 64 + qi) * 4;
    const int r0 = half * 16;

    if (tid < 16) {
        float s = 0.f;
        for (int sp = 0; sp < ns; sp++)
            s += g_lacc[(slice0 + sp) * 32 + r0 + tid];
        ls[tid] = 1.f / s;
    }
    __syncthreads();

    {
        int row = tid >> 4, c4 = tid & 15;      // row 0..15, c4 0..15
        float4 s = make_float4(0.f, 0.f, 0.f, 0.f);
        for (int sp = 0; sp < ns; sp++) {
            float4 v = *(const float4*)&g_oacc[(slice0 + sp) * 2048 +
                                               (r0 + row) * 64 + c4 * 4];
            s.x += v.x; s.y += v.y; s.z += v.z; s.w += v.w;
        }
        float li = ls[row];
        s.x *= li; s.y *= li; s.z *= li; s.w *= li;
        *(float4*)&out[((size_t)b * NT + qi * 32 + r0 + row) * D + c4 * 4] = s;
    }
}

// ---------------------------------------------------------------------------
// Inputs (dict order): K, Q, V, Wk, Wq, Wv.  Output [B, NT, D] fp32.
// ---------------------------------------------------------------------------
extern "C" void kernel_launch(void* const* d_in, const int* in_sizes, int n_in,
                              void* d_out, int out_size)
{
    const float* Kin = (const float*)d_in[0];
    const float* Qin = (const float*)d_in[1];
    const float* Vin = (const float*)d_in[2];
    const float* Wk  = (const float*)d_in[3];
    const float* Wq  = (const float*)d_in[4];
    const float* Wv  = (const float*)d_in[5];
    float* out = (float*)d_out;
    (void)in_sizes; (void)n_in; (void)out_size;

    cudaFuncSetAttribute(proj_kernel,
                         cudaFuncAttributeMaxDynamicSharedMemorySize,
                         P_SMEM_BYTES);
    cudaFuncSetAttribute(attn_partial_kernel,
                         cudaFuncAttributeMaxDynamicSharedMemorySize,
                         A_SMEM_BYTES);

    dim3 pgrid(128, 3, 2);
    proj_kernel<<<pgrid, 256, P_SMEM_BYTES>>>(Kin, Qin, Vin, Wk, Wq, Wv);

    dim3 rgrid(512, 3);
    proj_reduce_kernel<<<rgrid, 256>>>();

    dim3 agrid(160, BATCH);
    attn_partial_kernel<<<agrid, 128, A_SMEM_BYTES>>>();

    dim3 fgrid(128, BATCH);
    finalize_kernel<<<fgrid, 256>>>(out);
}